// round 16
// baseline (speedup 1.0000x reference)
#include <cuda_runtime.h>
#include <cuda_bf16.h>

#define N_ROWS 256
#define D_COLS 8192
#define LAMBDA 0.005f
#define SPLITS 24
#define NTILES 3              // symmetric 128x128 tile pairs: (0,0),(0,1),(1,1)
#define TILE_ELEMS 16384
#define BK 64                 // k per mainloop iter == stats chunk width
#define LDB 72                // smem row stride in bf16 (144 B, odd granule count -> conflict-free)
#define TILE_BUF 18432        // 128 * 144 B, one side one stage
#define NSTAGE 3
#define A_REGION (NSTAGE * TILE_BUF)      // 55296
#define DYN_SMEM (2 * NSTAGE * TILE_BUF)  // 110592
#define NBLK 148
#define NTHR 512
#define CROSS_TASKS 12288     // 3*TILE_ELEMS/4 float4 tasks
#define NCROSSBLK 96          // 96 blocks x 128 tasks = 12288
#define SGRP 4                // split groups (6 splits each)
#define CR_STRIDE 36          // smem floats per task slot

// ---- scratch ----
__device__ __align__(16) __nv_bfloat16 g_Zn[2][N_ROWS * D_COLS];      // normalized bf16, 8 MB
__device__ float g_diag[128];
__device__ __align__(16) float g_GP[2][SPLITS][NTILES * TILE_ELEMS];  // 9.4 MB partials
__device__ float g_red[NBLK];
__device__ unsigned g_flag[128];    // per-k-chunk ready flags (reset in-kernel)
__device__ unsigned g_bar_count;
__device__ unsigned g_bar_gen;
__device__ unsigned g_fin;

// ---------------------------------------------------------------------------
__device__ __forceinline__ void grid_sync() {
    __syncthreads();
    if (threadIdx.x == 0) {
        __threadfence();
        const unsigned gen = *(volatile unsigned*)&g_bar_gen;
        if (atomicAdd(&g_bar_count, 1u) == NBLK - 1) {
            g_bar_count = 0;
            __threadfence();
            *(volatile unsigned*)&g_bar_gen = gen + 1;
        } else {
            while (*(volatile unsigned*)&g_bar_gen == gen) {}
        }
        __threadfence();
    }
    __syncthreads();
}

__device__ __forceinline__ void mma_bf16(float* c, const unsigned* a, unsigned b0, unsigned b1) {
    asm volatile(
        "mma.sync.aligned.m16n8k16.row.col.f32.bf16.bf16.f32 "
        "{%0,%1,%2,%3}, {%4,%5,%6,%7}, {%8,%9}, {%0,%1,%2,%3};\n"
        : "+f"(c[0]), "+f"(c[1]), "+f"(c[2]), "+f"(c[3])
        : "r"(a[0]), "r"(a[1]), "r"(a[2]), "r"(a[3]), "r"(b0), "r"(b1));
}
__device__ __forceinline__ void ldm4(unsigned* r, unsigned addr) {
    asm volatile("ldmatrix.sync.aligned.m8n8.x4.shared.b16 {%0,%1,%2,%3}, [%4];\n"
        : "=r"(r[0]), "=r"(r[1]), "=r"(r[2]), "=r"(r[3]) : "r"(addr));
}
__device__ __forceinline__ void cp_async16(unsigned dst, const void* src) {
    asm volatile("cp.async.cg.shared.global [%0], [%1], 16;\n" :: "r"(dst), "l"(src));
}

// block-wide wait until k-chunk `ch` of g_Zn is published
__device__ __forceinline__ void chunk_wait(int ch) {
    if (threadIdx.x == 0) {
        while (*(volatile unsigned*)&g_flag[ch] == 0u) { __nanosleep(32); }
        __threadfence();
    }
    __syncthreads();
}

__global__ __launch_bounds__(NTHR, 1)
void fused_kernel(const float* __restrict__ za, const float* __restrict__ zb,
                  float* __restrict__ out) {
    extern __shared__ __align__(16) unsigned char dyn[];
    __shared__ float s_red[NTHR];
    __shared__ unsigned s_last;

    const int bid = blockIdx.x;
    const int tid = threadIdx.x;

    // ========== Phase 0 (bid<128): single-pass float4 stats+normalize+diag ==
    // Block b produces normalized k-chunk b (cols b*64..b*64+63), then flags it.
    if (bid < 128) {
        float* s_stf = (float*)dyn;                                        // [32][16][20]
        float* s_mu = (float*)(dyn + 40960);                               // [2][64]
        float* s_inv = (float*)(dyn + 40960 + 512);                        // [2][64]

        const int cq = tid & 15;          // column quad (4 cols)
        const int rg = tid >> 4;          // 0..31, 8 rows each
        const int col0 = bid * 64 + cq * 4;
        const float* __restrict__ pa = za + (size_t)(rg * 8) * D_COLS + col0;
        const float* __restrict__ pb = zb + (size_t)(rg * 8) * D_COLS + col0;

        float4 va[8], vb[8];
#pragma unroll
        for (int n = 0; n < 8; ++n) {
            va[n] = *(const float4*)&pa[n * D_COLS];
            vb[n] = *(const float4*)&pb[n * D_COLS];
        }
        float4 sa = {0,0,0,0}, sb = {0,0,0,0}, saa = {0,0,0,0}, sbb = {0,0,0,0}, sab = {0,0,0,0};
#pragma unroll
        for (int n = 0; n < 8; ++n) {
            sa.x += va[n].x; sa.y += va[n].y; sa.z += va[n].z; sa.w += va[n].w;
            sb.x += vb[n].x; sb.y += vb[n].y; sb.z += vb[n].z; sb.w += vb[n].w;
            saa.x += va[n].x * va[n].x; saa.y += va[n].y * va[n].y;
            saa.z += va[n].z * va[n].z; saa.w += va[n].w * va[n].w;
            sbb.x += vb[n].x * vb[n].x; sbb.y += vb[n].y * vb[n].y;
            sbb.z += vb[n].z * vb[n].z; sbb.w += vb[n].w * vb[n].w;
            sab.x += va[n].x * vb[n].x; sab.y += va[n].y * vb[n].y;
            sab.z += va[n].z * vb[n].z; sab.w += va[n].w * vb[n].w;
        }
        {
            float* p = &s_stf[(rg * 16 + cq) * 20];
            *(float4*)&p[0] = sa;  *(float4*)&p[4] = sb;
            *(float4*)&p[8] = saa; *(float4*)&p[12] = sbb; *(float4*)&p[16] = sab;
        }
        __syncthreads();

        float term = 0.f;
        if (tid < 64) {
            const int c = tid;
            const int q = c >> 2, j = c & 3;
            float t0 = 0.f, t1 = 0.f, t2 = 0.f, t3 = 0.f, t4 = 0.f;
#pragma unroll 8
            for (int g = 0; g < 32; ++g) {
                const float* p = &s_stf[(g * 16 + q) * 20];
                t0 += p[j]; t1 += p[4 + j]; t2 += p[8 + j]; t3 += p[12 + j]; t4 += p[16 + j];
            }
            const float mua = t0 * (1.f / 256.f);
            const float mub = t1 * (1.f / 256.f);
            const float ia = rsqrtf((t2 - t0 * mua) * (1.f / 255.f));
            const float ib = rsqrtf((t3 - t1 * mub) * (1.f / 255.f));
            const float cdd = (t4 - 256.f * mua * mub) * ia * ib * (1.f / 256.f);
            term = (cdd - 1.f) * (cdd - 1.f) - LAMBDA * cdd * cdd;
            s_mu[c] = mua; s_mu[64 + c] = mub;
            s_inv[c] = ia; s_inv[64 + c] = ib;
        }
        s_red[tid] = term;
        __syncthreads();
#pragma unroll
        for (int off = 32; off > 0; off >>= 1) {   // data only in tids 0..63
            if (tid < off) s_red[tid] += s_red[tid + off];
            __syncthreads();
        }
        if (tid == 0) g_diag[bid] = s_red[0];

        // normalize from registers, write bf16 (4 cols = uint2 per row)
        const float4 ma = *(const float4*)&s_mu[cq * 4];
        const float4 wa = *(const float4*)&s_inv[cq * 4];
        const float4 mb = *(const float4*)&s_mu[64 + cq * 4];
        const float4 wb = *(const float4*)&s_inv[64 + cq * 4];
        __nv_bfloat16* __restrict__ oa = g_Zn[0] + (size_t)(rg * 8) * D_COLS + col0;
        __nv_bfloat16* __restrict__ ob = g_Zn[1] + (size_t)(rg * 8) * D_COLS + col0;
#pragma unroll
        for (int n = 0; n < 8; ++n) {
            union { __nv_bfloat162 h2[2]; uint2 u; } ua, ub;
            ua.h2[0] = __floats2bfloat162_rn((va[n].x - ma.x) * wa.x, (va[n].y - ma.y) * wa.y);
            ua.h2[1] = __floats2bfloat162_rn((va[n].z - ma.z) * wa.z, (va[n].w - ma.w) * wa.w);
            ub.h2[0] = __floats2bfloat162_rn((vb[n].x - mb.x) * wb.x, (vb[n].y - mb.y) * wb.y);
            ub.h2[1] = __floats2bfloat162_rn((vb[n].z - mb.z) * wb.z, (vb[n].w - mb.w) * wb.w);
            *(uint2*)&oa[n * D_COLS] = ua.u;
            *(uint2*)&ob[n * D_COLS] = ub.u;
        }

        // publish chunk `bid`
        __threadfence();
        __syncthreads();
        if (tid == 0) *(volatile unsigned*)&g_flag[bid] = 1u;
    }

    // NO grid_sync here — gram is gated per-chunk by flags, self-aligned.

    // ========== Phase 1 (bid<144): gram, rotated chunk order ================
    if (bid < 2 * NTILES * SPLITS) {
        // decode (s, jj): block's gram work; jj -> (sel,pair); start chunk = own
        int s, jj;
        if (bid < 128) {
            s = (bid < 80) ? (bid / 5) : 16 + (bid - 80) / 6;
            const int ksl = (s < 16) ? s * 5 : 80 + (s - 16) * 6;
            jj = bid - ksl;                 // 0..kn-1
        } else {
            s = bid - 128;                  // 0..15 (kn=5 splits), overflow work
            jj = 5;
        }
        const int sel = jj / 3;             // 0..1
        const int pair = jj % 3;            // 0..2
        const bool dup = (pair != 1);       // diagonal tile pairs: B tile == A tile

        const int m0 = (pair == 2) ? 128 : 0;
        const int n0 = (pair == 0) ? 0 : 128;
        const int ks = (s < 16) ? s * 5 : 80 + (s - 16) * 6;
        const int kn = (s < 16) ? 5 : 6;
        const int j0 = jj % kn;             // rotated start offset (own chunk first)

        const __nv_bfloat16* __restrict__ gA = g_Zn[sel] + (size_t)m0 * D_COLS;
        const __nv_bfloat16* __restrict__ gB = g_Zn[sel] + (size_t)n0 * D_COLS;

        const int warp = tid >> 5;
        const int lane = tid & 31;
        const int wm = warp & 3;    // 4 m-strips of 32
        const int wn = warp >> 2;   // 4 n-strips of 32

        float acc[2][4][4];
#pragma unroll
        for (int i = 0; i < 2; ++i)
#pragma unroll
            for (int j = 0; j < 4; ++j)
#pragma unroll
                for (int k = 0; k < 4; ++k) acc[i][j][k] = 0.f;

        const unsigned sBase = (unsigned)__cvta_generic_to_shared(dyn);
        const unsigned bRegion = dup ? sBase : (sBase + (unsigned)A_REGION);
        const int laR = (lane & 7) + (lane & 8);
        const int laC = (lane >> 1) & 8;
        const int lbR = (lane & 7) + ((lane >> 1) & 8);
        const int lbC = (lane & 8);
        const unsigned aAddr = sBase + (unsigned)(((wm * 32 + laR) * LDB + laC) * 2);
        const unsigned bAddr = bRegion + (unsigned)(((wn * 32 + lbR) * LDB + lbC) * 2);

        // chunk index for iteration it (rotated so it=0 is this block's own chunk)
#define CHUNK(itv) (ks + ((j0 + (itv)) % kn))

#define STAGE(slot, chv)                                                          \
        {                                                                         \
            const int k0_ = (chv) * BK;                                           \
            const unsigned so_ = (unsigned)(slot) * TILE_BUF;                     \
            _Pragma("unroll")                                                     \
            for (int i_ = 0; i_ < 2; ++i_) {                                      \
                const int l_ = i_ * NTHR + tid;                                   \
                const int r_ = l_ >> 3;                                           \
                const int c_ = l_ & 7;                                            \
                cp_async16(sBase + so_ + (unsigned)(r_ * 144 + c_ * 16),          \
                           gA + (size_t)r_ * D_COLS + k0_ + c_ * 8);              \
                if (!dup)                                                         \
                    cp_async16(sBase + (unsigned)A_REGION + so_ + (unsigned)(r_ * 144 + c_ * 16), \
                               gB + (size_t)r_ * D_COLS + k0_ + c_ * 8);          \
            }                                                                     \
            asm volatile("cp.async.commit_group;\n");                             \
        }

        chunk_wait(CHUNK(0));   // own chunk for bid<128 -> already set
        STAGE(0, CHUNK(0));
        chunk_wait(CHUNK(1));
        STAGE(1, CHUNK(1));
        for (int it = 0; it < kn; ++it) {
            if (it == kn - 1) { asm volatile("cp.async.wait_group 0;\n"); }
            else              { asm volatile("cp.async.wait_group 1;\n"); }
            __syncthreads();   // orders prev slot reads + this chunk's data
            if (it + 2 < kn) {
                chunk_wait(CHUNK(it + 2));
                STAGE((it + 2) % NSTAGE, CHUNK(it + 2));
            }

            const unsigned off = (unsigned)((it % NSTAGE) * TILE_BUF);
#pragma unroll
            for (int kf = 0; kf < 4; ++kf) {
                unsigned A0[4], A1[4];
                ldm4(A0, aAddr + off + (unsigned)(kf * 32));
                ldm4(A1, aAddr + off + (unsigned)(16 * LDB * 2 + kf * 32));
#pragma unroll
                for (int fp = 0; fp < 2; ++fp) {
                    unsigned B[4];
                    ldm4(B, bAddr + off + (unsigned)(fp * 16 * LDB * 2 + kf * 32));
                    mma_bf16(acc[0][2 * fp],     A0, B[0], B[1]);
                    mma_bf16(acc[0][2 * fp + 1], A0, B[2], B[3]);
                    mma_bf16(acc[1][2 * fp],     A1, B[0], B[1]);
                    mma_bf16(acc[1][2 * fp + 1], A1, B[2], B[3]);
                }
            }
        }
#undef STAGE
#undef CHUNK

        float* __restrict__ outp = &g_GP[sel][s][pair * TILE_ELEMS];
#pragma unroll
        for (int fm = 0; fm < 2; ++fm)
#pragma unroll
            for (int fn = 0; fn < 4; ++fn) {
                const int i = wm * 32 + fm * 16 + (lane >> 2);
                const int j = wn * 32 + fn * 8 + (lane & 3) * 2;
                float2 lo = {acc[fm][fn][0], acc[fm][fn][1]};
                float2 hi = {acc[fm][fn][2], acc[fm][fn][3]};
                *(float2*)&outp[i * 128 + j] = lo;
                *(float2*)&outp[(i + 8) * 128 + j] = hi;
            }
    }

    grid_sync();

    // reset flags for next graph replay (all flag reads happened before the sync)
    if (bid < 128 && tid == 0) g_flag[bid] = 0u;

    // ========== Phase 2: cross reduction, split-group parallel + fused final =
    {
        float v = 0.f;
        if (bid < NCROSSBLK) {
            const int tl = tid & 127;
            const int grp = tid >> 7;                 // 0..3, 6 splits each
            const int t = bid * 128 + tl;             // float4 task 0..12287
            float4 ga = {0.f, 0.f, 0.f, 0.f}, gb = {0.f, 0.f, 0.f, 0.f};
#pragma unroll
            for (int q = 0; q < 6; ++q) {
                const int s = grp * 6 + q;
                const float4 a = *(const float4*)&g_GP[0][s][t * 4];
                const float4 bb = *(const float4*)&g_GP[1][s][t * 4];
                ga.x += a.x; ga.y += a.y; ga.z += a.z; ga.w += a.w;
                gb.x += bb.x; gb.y += bb.y; gb.z += bb.z; gb.w += bb.w;
            }
            float* sm = (float*)dyn;                  // [128][CR_STRIDE]
            *(float4*)&sm[tl * CR_STRIDE + grp * 8 + 0] = ga;
            *(float4*)&sm[tl * CR_STRIDE + grp * 8 + 4] = gb;
            __syncthreads();
            if (grp == 0) {
                float4 GA = {0.f, 0.f, 0.f, 0.f}, GB = {0.f, 0.f, 0.f, 0.f};
#pragma unroll
                for (int g = 0; g < SGRP; ++g) {
                    const float4 a = *(const float4*)&sm[tl * CR_STRIDE + g * 8 + 0];
                    const float4 b = *(const float4*)&sm[tl * CR_STRIDE + g * 8 + 4];
                    GA.x += a.x; GA.y += a.y; GA.z += a.z; GA.w += a.w;
                    GB.x += b.x; GB.y += b.y; GB.z += b.z; GB.w += b.w;
                }
                const float w = ((t >> 12) == 1) ? 2.f : 1.f;
                v = w * (GA.x * GB.x + GA.y * GB.y + GA.z * GB.z + GA.w * GB.w);
            }
        } else {
            __syncthreads();
        }
        __syncthreads();
        s_red[tid] = v;
        __syncthreads();
#pragma unroll
        for (int off = 64; off > 0; off >>= 1) {   // data only in tids 0..127
            if (tid < off) s_red[tid] += s_red[tid + off];
            __syncthreads();
        }
        if (tid == 0) {
            g_red[bid] = s_red[0];
            __threadfence();
            s_last = (atomicAdd(&g_fin, 1u) == NBLK - 1) ? 1u : 0u;
        }
        __syncthreads();

        if (s_last) {
            __threadfence();
            float v2 = 0.f;
            if (tid < NBLK) v2 = (*(volatile float*)&g_red[tid]) * (LAMBDA / (256.f * 256.f));
            if (tid < 128) v2 += *(volatile float*)&g_diag[tid];
            s_red[tid] = v2;
            __syncthreads();
#pragma unroll
            for (int off = 128; off > 0; off >>= 1) {   // data in tids 0..147 (<256)
                if (tid < off) s_red[tid] += s_red[tid + off];
                __syncthreads();
            }
            if (tid == 0) {
                out[0] = s_red[0];
                g_fin = 0;   // reset for next graph replay
            }
        }
    }
}

// ---------------------------------------------------------------------------
extern "C" void kernel_launch(void* const* d_in, const int* in_sizes, int n_in,
                              void* d_out, int out_size) {
    const float* za = (const float*)d_in[0];
    const float* zb = (const float*)d_in[1];
    float* out = (float*)d_out;
    cudaFuncSetAttribute(fused_kernel, cudaFuncAttributeMaxDynamicSharedMemorySize, DYN_SMEM);
    fused_kernel<<<NBLK, NTHR, DYN_SMEM>>>(za, zb, out);
}

// round 17
// speedup vs baseline: 1.2326x; 1.2326x over previous
#include <cuda_runtime.h>
#include <cuda_bf16.h>

#define N_ROWS 256
#define D_COLS 8192
#define LAMBDA 0.005f
#define SPLITS 24
#define NTILES 3              // symmetric 128x128 tile pairs: (0,0),(0,1),(1,1)
#define TILE_ELEMS 16384
#define BK 64                 // k per mainloop iter == chunk width
#define LDB 72                // row stride in bf16 (144 B, odd granule count -> conflict-free)
#define TILE_BUF 18432        // 128 rows * 144 B, one side one stage
#define NSTAGE 3
#define A_REGION (NSTAGE * TILE_BUF)      // 55296
#define DYN_SMEM (2 * NSTAGE * TILE_BUF)  // 110592
#define NBLK 148
#define NTHR 512
#define NCHUNK 128
#define CROSS_TASKS 12288     // 3*TILE_ELEMS/4 float4 tasks
#define NCROSSBLK 96          // 96 blocks x 128 tasks = 12288
#define SGRP 4                // split groups (6 splits each)
#define CR_STRIDE 36          // smem floats per task slot

// ---- scratch ----
// chunk-major normalized storage: [sel][chunk][row][LDB] (pad cols 64..71 unused)
__device__ __align__(16) __nv_bfloat16 g_Zn[2][NCHUNK * N_ROWS * LDB];   // 18.9 MB
__device__ float g_diag[128];
__device__ __align__(16) float g_GP[2][SPLITS][NTILES * TILE_ELEMS];      // 9.4 MB partials
__device__ float g_red[NBLK];
__device__ unsigned g_bar_count;
__device__ unsigned g_bar_gen;
__device__ unsigned g_fin;

// ---------------------------------------------------------------------------
__device__ __forceinline__ void grid_sync() {
    __syncthreads();
    if (threadIdx.x == 0) {
        __threadfence();
        const unsigned gen = *(volatile unsigned*)&g_bar_gen;
        if (atomicAdd(&g_bar_count, 1u) == NBLK - 1) {
            g_bar_count = 0;
            __threadfence();
            *(volatile unsigned*)&g_bar_gen = gen + 1;
        } else {
            while (*(volatile unsigned*)&g_bar_gen == gen) {}
        }
        __threadfence();
    }
    __syncthreads();
}

__device__ __forceinline__ void mma_bf16(float* c, const unsigned* a, unsigned b0, unsigned b1) {
    asm volatile(
        "mma.sync.aligned.m16n8k16.row.col.f32.bf16.bf16.f32 "
        "{%0,%1,%2,%3}, {%4,%5,%6,%7}, {%8,%9}, {%0,%1,%2,%3};\n"
        : "+f"(c[0]), "+f"(c[1]), "+f"(c[2]), "+f"(c[3])
        : "r"(a[0]), "r"(a[1]), "r"(a[2]), "r"(a[3]), "r"(b0), "r"(b1));
}
__device__ __forceinline__ void ldm4(unsigned* r, unsigned addr) {
    asm volatile("ldmatrix.sync.aligned.m8n8.x4.shared.b16 {%0,%1,%2,%3}, [%4];\n"
        : "=r"(r[0]), "=r"(r[1]), "=r"(r[2]), "=r"(r[3]) : "r"(addr));
}
// 1D bulk copy gmem->smem completing on an mbarrier (sm_90+ base ISA)
__device__ __forceinline__ void bulk_copy(unsigned dst, const void* src, unsigned bytes, unsigned mbar) {
    asm volatile(
        "cp.async.bulk.shared::cta.global.mbarrier::complete_tx::bytes [%0], [%1], %2, [%3];"
        :: "r"(dst), "l"(src), "r"(bytes), "r"(mbar) : "memory");
}
__device__ __forceinline__ void mbar_expect_tx(unsigned mbar, unsigned bytes) {
    asm volatile("mbarrier.arrive.expect_tx.shared.b64 _, [%0], %1;"
        :: "r"(mbar), "r"(bytes) : "memory");
}
__device__ __forceinline__ void mbar_wait(unsigned mbar, unsigned parity) {
    asm volatile(
        "{\n\t.reg .pred P;\n"
        "W%=:\n\tmbarrier.try_wait.parity.shared.b64 P, [%0], %1;\n"
        "\t@P bra D%=;\n\tbra W%=;\n"
        "D%=:\n\t}"
        :: "r"(mbar), "r"(parity) : "memory");
}

__global__ __launch_bounds__(NTHR, 1)
void fused_kernel(const float* __restrict__ za, const float* __restrict__ zb,
                  float* __restrict__ out) {
    extern __shared__ __align__(16) unsigned char dyn[];
    __shared__ float s_red[NTHR];
    __shared__ unsigned s_last;
    __shared__ __align__(8) unsigned long long s_mbar[NSTAGE];

    const int bid = blockIdx.x;
    const int tid = threadIdx.x;

    // ========== Phase 0 (bid<128): single-pass float4 stats+normalize+diag ==
    // Block b produces chunk b of g_Zn (cols b*64..b*64+63) in chunk-major layout.
    if (bid < 128) {
        float* s_stf = (float*)dyn;                                        // [32][16][20]
        float* s_mu = (float*)(dyn + 40960);                               // [2][64]
        float* s_inv = (float*)(dyn + 40960 + 512);                        // [2][64]

        const int cq = tid & 15;          // column quad (4 cols)
        const int rg = tid >> 4;          // 0..31, 8 rows each
        const int col0 = bid * 64 + cq * 4;
        const float* __restrict__ pa = za + (size_t)(rg * 8) * D_COLS + col0;
        const float* __restrict__ pb = zb + (size_t)(rg * 8) * D_COLS + col0;

        float4 va[8], vb[8];
#pragma unroll
        for (int n = 0; n < 8; ++n) {
            va[n] = *(const float4*)&pa[n * D_COLS];
            vb[n] = *(const float4*)&pb[n * D_COLS];
        }
        float4 sa = {0,0,0,0}, sb = {0,0,0,0}, saa = {0,0,0,0}, sbb = {0,0,0,0}, sab = {0,0,0,0};
#pragma unroll
        for (int n = 0; n < 8; ++n) {
            sa.x += va[n].x; sa.y += va[n].y; sa.z += va[n].z; sa.w += va[n].w;
            sb.x += vb[n].x; sb.y += vb[n].y; sb.z += vb[n].z; sb.w += vb[n].w;
            saa.x += va[n].x * va[n].x; saa.y += va[n].y * va[n].y;
            saa.z += va[n].z * va[n].z; saa.w += va[n].w * va[n].w;
            sbb.x += vb[n].x * vb[n].x; sbb.y += vb[n].y * vb[n].y;
            sbb.z += vb[n].z * vb[n].z; sbb.w += vb[n].w * vb[n].w;
            sab.x += va[n].x * vb[n].x; sab.y += va[n].y * vb[n].y;
            sab.z += va[n].z * vb[n].z; sab.w += va[n].w * vb[n].w;
        }
        {
            float* p = &s_stf[(rg * 16 + cq) * 20];
            *(float4*)&p[0] = sa;  *(float4*)&p[4] = sb;
            *(float4*)&p[8] = saa; *(float4*)&p[12] = sbb; *(float4*)&p[16] = sab;
        }
        __syncthreads();

        float term = 0.f;
        if (tid < 64) {
            const int c = tid;
            const int q = c >> 2, j = c & 3;
            float t0 = 0.f, t1 = 0.f, t2 = 0.f, t3 = 0.f, t4 = 0.f;
#pragma unroll 8
            for (int g = 0; g < 32; ++g) {
                const float* p = &s_stf[(g * 16 + q) * 20];
                t0 += p[j]; t1 += p[4 + j]; t2 += p[8 + j]; t3 += p[12 + j]; t4 += p[16 + j];
            }
            const float mua = t0 * (1.f / 256.f);
            const float mub = t1 * (1.f / 256.f);
            const float ia = rsqrtf((t2 - t0 * mua) * (1.f / 255.f));
            const float ib = rsqrtf((t3 - t1 * mub) * (1.f / 255.f));
            const float cdd = (t4 - 256.f * mua * mub) * ia * ib * (1.f / 256.f);
            term = (cdd - 1.f) * (cdd - 1.f) - LAMBDA * cdd * cdd;
            s_mu[c] = mua; s_mu[64 + c] = mub;
            s_inv[c] = ia; s_inv[64 + c] = ib;
        }
        s_red[tid] = term;
        __syncthreads();
#pragma unroll
        for (int off = 32; off > 0; off >>= 1) {   // data only in tids 0..63
            if (tid < off) s_red[tid] += s_red[tid + off];
            __syncthreads();
        }
        if (tid == 0) g_diag[bid] = s_red[0];

        // normalize from registers; write bf16 chunk-major (LDB=72 rows)
        const float4 ma = *(const float4*)&s_mu[cq * 4];
        const float4 wa = *(const float4*)&s_inv[cq * 4];
        const float4 mb = *(const float4*)&s_mu[64 + cq * 4];
        const float4 wb = *(const float4*)&s_inv[64 + cq * 4];
        __nv_bfloat16* __restrict__ oa = g_Zn[0] + ((size_t)bid * N_ROWS + rg * 8) * LDB + cq * 4;
        __nv_bfloat16* __restrict__ ob = g_Zn[1] + ((size_t)bid * N_ROWS + rg * 8) * LDB + cq * 4;
#pragma unroll
        for (int n = 0; n < 8; ++n) {
            union { __nv_bfloat162 h2[2]; uint2 u; } ua, ub;
            ua.h2[0] = __floats2bfloat162_rn((va[n].x - ma.x) * wa.x, (va[n].y - ma.y) * wa.y);
            ua.h2[1] = __floats2bfloat162_rn((va[n].z - ma.z) * wa.z, (va[n].w - ma.w) * wa.w);
            ub.h2[0] = __floats2bfloat162_rn((vb[n].x - mb.x) * wb.x, (vb[n].y - mb.y) * wb.y);
            ub.h2[1] = __floats2bfloat162_rn((vb[n].z - mb.z) * wb.z, (vb[n].w - mb.w) * wb.w);
            *(uint2*)&oa[n * LDB] = ua.u;
            *(uint2*)&ob[n * LDB] = ub.u;
        }
    }

    grid_sync();

    // ========== Phase 1 (bid<144): bulk-copy staged tensor-core Gram ========
    // 16 warps, 4x4 warp grid, 32x32 warp tiles, BK=64; staging = 1-2
    // cp.async.bulk per iter issued by tid 0, completing on per-slot mbarriers.
    if (bid < 2 * NTILES * SPLITS) {
        const int sel = bid / (NTILES * SPLITS);
        const int rem = bid % (NTILES * SPLITS);
        const int pair = rem / SPLITS;
        const int s = rem % SPLITS;
        const bool dup = (pair != 1);      // diagonal tile pairs: B tile == A tile

        const int m0 = (pair == 2) ? 128 : 0;
        const int n0 = (pair == 0) ? 0 : 128;
        // 128 k-chunks of 64: splits 0..15 get 5, 16..23 get 6
        const int ks = (s < 16) ? s * 5 : 80 + (s - 16) * 6;
        const int kn = (s < 16) ? 5 : 6;

        const __nv_bfloat16* __restrict__ Z = g_Zn[sel];
        const unsigned xferBytes = dup ? (unsigned)TILE_BUF : 2u * TILE_BUF;

        const int warp = tid >> 5;
        const int lane = tid & 31;
        const int wm = warp & 3;    // 4 m-strips of 32
        const int wn = warp >> 2;   // 4 n-strips of 32

        float acc[2][4][4];
#pragma unroll
        for (int i = 0; i < 2; ++i)
#pragma unroll
            for (int j = 0; j < 4; ++j)
#pragma unroll
                for (int k = 0; k < 4; ++k) acc[i][j][k] = 0.f;

        const unsigned sBase = (unsigned)__cvta_generic_to_shared(dyn);
        const unsigned bRegion = dup ? sBase : (sBase + (unsigned)A_REGION);
        const unsigned mb0 = (unsigned)__cvta_generic_to_shared(&s_mbar[0]);
        const int laR = (lane & 7) + (lane & 8);
        const int laC = (lane >> 1) & 8;
        const int lbR = (lane & 7) + ((lane >> 1) & 8);
        const int lbC = (lane & 8);
        const unsigned aAddr = sBase + (unsigned)(((wm * 32 + laR) * LDB + laC) * 2);
        const unsigned bAddr = bRegion + (unsigned)(((wn * 32 + lbR) * LDB + lbC) * 2);

        // init per-slot mbarriers (count 1: single producer arrives via expect_tx)
        if (tid == 0) {
#pragma unroll
            for (int q = 0; q < NSTAGE; ++q)
                asm volatile("mbarrier.init.shared.b64 [%0], 1;" :: "r"(mb0 + 8u * q) : "memory");
        }
        __syncthreads();

        // stage chunk (ks+kidx) into slot: A rows m0.., B rows n0.. (skip if dup)
#define STAGE(slot, kidx)                                                         \
        {                                                                         \
            const unsigned mb_ = mb0 + 8u * (slot);                               \
            const unsigned so_ = (unsigned)(slot) * TILE_BUF;                     \
            const size_t chBase_ = (size_t)(ks + (kidx)) * N_ROWS * LDB;          \
            mbar_expect_tx(mb_, xferBytes);                                       \
            bulk_copy(sBase + so_, Z + chBase_ + (size_t)m0 * LDB, TILE_BUF, mb_);\
            if (!dup)                                                             \
                bulk_copy(sBase + (unsigned)A_REGION + so_,                       \
                          Z + chBase_ + (size_t)n0 * LDB, TILE_BUF, mb_);         \
        }

        if (tid == 0) { STAGE(0, 0); STAGE(1, 1); }
        for (int it = 0; it < kn; ++it) {
            mbar_wait(mb0 + 8u * (it % NSTAGE), (unsigned)((it / NSTAGE) & 1));
            __syncthreads();   // all threads past iter it-1 reads (slot (it+2)%3)
            if (tid == 0 && it + 2 < kn) STAGE((it + 2) % NSTAGE, it + 2);

            const unsigned off = (unsigned)((it % NSTAGE) * TILE_BUF);
#pragma unroll
            for (int kf = 0; kf < 4; ++kf) {
                unsigned A0[4], A1[4];
                ldm4(A0, aAddr + off + (unsigned)(kf * 32));
                ldm4(A1, aAddr + off + (unsigned)(16 * LDB * 2 + kf * 32));
#pragma unroll
                for (int fp = 0; fp < 2; ++fp) {
                    unsigned B[4];
                    ldm4(B, bAddr + off + (unsigned)(fp * 16 * LDB * 2 + kf * 32));
                    mma_bf16(acc[0][2 * fp],     A0, B[0], B[1]);
                    mma_bf16(acc[0][2 * fp + 1], A0, B[2], B[3]);
                    mma_bf16(acc[1][2 * fp],     A1, B[0], B[1]);
                    mma_bf16(acc[1][2 * fp + 1], A1, B[2], B[3]);
                }
            }
        }
#undef STAGE

        float* __restrict__ outp = &g_GP[sel][s][pair * TILE_ELEMS];
#pragma unroll
        for (int fm = 0; fm < 2; ++fm)
#pragma unroll
            for (int fn = 0; fn < 4; ++fn) {
                const int i = wm * 32 + fm * 16 + (lane >> 2);
                const int j = wn * 32 + fn * 8 + (lane & 3) * 2;
                float2 lo = {acc[fm][fn][0], acc[fm][fn][1]};
                float2 hi = {acc[fm][fn][2], acc[fm][fn][3]};
                *(float2*)&outp[i * 128 + j] = lo;
                *(float2*)&outp[(i + 8) * 128 + j] = hi;
            }
    }

    grid_sync();

    // ========== Phase 2: cross reduction, split-group parallel + fused final =
    {
        float v = 0.f;
        if (bid < NCROSSBLK) {
            const int tl = tid & 127;
            const int grp = tid >> 7;                 // 0..3, 6 splits each
            const int t = bid * 128 + tl;             // float4 task 0..12287
            float4 ga = {0.f, 0.f, 0.f, 0.f}, gb = {0.f, 0.f, 0.f, 0.f};
#pragma unroll
            for (int q = 0; q < 6; ++q) {
                const int s = grp * 6 + q;
                const float4 a = *(const float4*)&g_GP[0][s][t * 4];
                const float4 bb = *(const float4*)&g_GP[1][s][t * 4];
                ga.x += a.x; ga.y += a.y; ga.z += a.z; ga.w += a.w;
                gb.x += bb.x; gb.y += bb.y; gb.z += bb.z; gb.w += bb.w;
            }
            float* sm = (float*)dyn;                  // [128][CR_STRIDE]
            *(float4*)&sm[tl * CR_STRIDE + grp * 8 + 0] = ga;
            *(float4*)&sm[tl * CR_STRIDE + grp * 8 + 4] = gb;
            __syncthreads();
            if (grp == 0) {
                float4 GA = {0.f, 0.f, 0.f, 0.f}, GB = {0.f, 0.f, 0.f, 0.f};
#pragma unroll
                for (int g = 0; g < SGRP; ++g) {
                    const float4 a = *(const float4*)&sm[tl * CR_STRIDE + g * 8 + 0];
                    const float4 b = *(const float4*)&sm[tl * CR_STRIDE + g * 8 + 4];
                    GA.x += a.x; GA.y += a.y; GA.z += a.z; GA.w += a.w;
                    GB.x += b.x; GB.y += b.y; GB.z += b.z; GB.w += b.w;
                }
                const float w = ((t >> 12) == 1) ? 2.f : 1.f;
                v = w * (GA.x * GB.x + GA.y * GB.y + GA.z * GB.z + GA.w * GB.w);
            }
        } else {
            __syncthreads();
        }
        __syncthreads();
        s_red[tid] = v;
        __syncthreads();
#pragma unroll
        for (int off = 64; off > 0; off >>= 1) {   // data only in tids 0..127
            if (tid < off) s_red[tid] += s_red[tid + off];
            __syncthreads();
        }
        if (tid == 0) {
            g_red[bid] = s_red[0];
            __threadfence();
            s_last = (atomicAdd(&g_fin, 1u) == NBLK - 1) ? 1u : 0u;
        }
        __syncthreads();

        if (s_last) {
            __threadfence();
            float v2 = 0.f;
            if (tid < NBLK) v2 = (*(volatile float*)&g_red[tid]) * (LAMBDA / (256.f * 256.f));
            if (tid < 128) v2 += *(volatile float*)&g_diag[tid];
            s_red[tid] = v2;
            __syncthreads();
#pragma unroll
            for (int off = 128; off > 0; off >>= 1) {   // data in tids 0..147 (<256)
                if (tid < off) s_red[tid] += s_red[tid + off];
                __syncthreads();
            }
            if (tid == 0) {
                out[0] = s_red[0];
                g_fin = 0;   // reset for next graph replay
            }
        }
    }
}

// ---------------------------------------------------------------------------
extern "C" void kernel_launch(void* const* d_in, const int* in_sizes, int n_in,
                              void* d_out, int out_size) {
    const float* za = (const float*)d_in[0];
    const float* zb = (const float*)d_in[1];
    float* out = (float*)d_out;
    cudaFuncSetAttribute(fused_kernel, cudaFuncAttributeMaxDynamicSharedMemorySize, DYN_SMEM);
    fused_kernel<<<NBLK, NTHR, DYN_SMEM>>>(za, zb, out);
}